// round 11
// baseline (speedup 1.0000x reference)
#include <cuda_runtime.h>
#include <math.h>

#define THREADS    128
#define QPT        4                 // queries per thread
#define QPB        (THREADS * QPT)   // 512 queries per block
#define TILE_PAIRS 384               // smem tile: 384 * 32B = 12,288 B
#define MAX_PPS    380               // pps <= 380; ceil(380/4)=95 <= 255 byte bound

typedef unsigned long long u64;
typedef unsigned int u32;

__device__ __forceinline__ u64 pk2(float a, float b) {
    u64 r; asm("mov.b64 %0, {%1, %2};" : "=l"(r) : "f"(a), "f"(b)); return r;
}

// One m-pair (2 m's in f32x2 lanes) vs one query: s = d2 - 0.25 per lane,
// then sign bytes via PRMT (one fused asm block; b64->b32 split is a rename).
// ctl 0x00FB -> sign bytes at {0,1}; 0xFB00 -> at {2,3}.
__device__ __forceinline__ u32 pair_sign(u64 X, u64 Y, u64 Z, u64 C,
                                         u64 bx2, u64 by2, u64 bz2, u64 b2p,
                                         u32 ctl) {
    u32 q;
    asm("{\n\t"
        ".reg .b64 t;\n\t"
        ".reg .b32 lo, hi;\n\t"
        "fma.rn.f32x2 t, %1, %2, %3;\n\t"     // t  = bx*X + C
        "fma.rn.f32x2 t, %4, %5, t;\n\t"      // t += by*Y
        "fma.rn.f32x2 t, %6, %7, t;\n\t"      // t += bz*Z
        "add.rn.f32x2 t, t, %8;\n\t"          // t += b2
        "mov.b64 {lo, hi}, t;\n\t"
        "prmt.b32 %0, lo, hi, %9;\n\t"
        "}"
        : "=r"(q)
        : "l"(bx2), "l"(X), "l"(C),
          "l"(by2), "l"(Y),
          "l"(bz2), "l"(Z),
          "l"(b2p), "r"(ctl));
    return q;
}

// s = b2 + (a2-0.25) - 2(x*bx+y*by+z*bz) = d2 - 0.25; count iff s < 0.
// Matches reference's sqrt(max(d2,0)) <= 0.5 up to reassociation ties
// (measured 8.1e-6).
__global__ void __launch_bounds__(THREADS) count_kernel(
    const float* __restrict__ pc,   // queries [N,3]
    const float* __restrict__ pad,  // padding [M,3]
    int N, int M, int pairs, int pps, float* __restrict__ out)
{
    __shared__ ulonglong2 sh[2 * TILE_PAIRS];   // per pair: {X01,Y01},{Z01,C01}
    const float INF = __int_as_float(0x7f800000);

    int p0 = blockIdx.y * pps;
    int np = pairs - p0;
    if (np > pps) np = pps;
    int np4 = (np + 3) & ~3;

    // Stage + pack this m-slice from raw padding data.
    for (int i = threadIdx.x; i < np; i += THREADS) {
        int p  = p0 + i;
        int m0 = 2 * p, m1 = 2 * p + 1;
        float x0 = pad[3 * m0], y0 = pad[3 * m0 + 1], z0 = pad[3 * m0 + 2];
        float c0 = fmaf(x0, x0, fmaf(y0, y0, z0 * z0)) - 0.25f;
        float x1 = 0.f, y1 = 0.f, z1 = 0.f, c1 = INF;   // sentinel never counts
        if (m1 < M) {
            x1 = pad[3 * m1]; y1 = pad[3 * m1 + 1]; z1 = pad[3 * m1 + 2];
            c1 = fmaf(x1, x1, fmaf(y1, y1, z1 * z1)) - 0.25f;
        }
        sh[2 * i]     = make_ulonglong2(pk2(-2.f * x0, -2.f * x1),
                                        pk2(-2.f * y0, -2.f * y1));
        sh[2 * i + 1] = make_ulonglong2(pk2(-2.f * z0, -2.f * z1),
                                        pk2(c0, c1));
    }
    for (int i = np + threadIdx.x; i < np4; i += THREADS) {
        sh[2 * i]     = make_ulonglong2(0ull, 0ull);
        sh[2 * i + 1] = make_ulonglong2(0ull, pk2(INF, INF));
    }
    __syncthreads();

    // 4 queries per thread: n0 + k*THREADS.
    int n0 = blockIdx.x * QPB + threadIdx.x;
    u64 bx2[QPT], by2[QPT], bz2[QPT], b2p[QPT];
#pragma unroll
    for (int k = 0; k < QPT; ++k) {
        int n = n0 + k * THREADS;
        float bx = 0.f, by = 0.f, bz = 0.f, b2 = INF;
        if (n < N) {
            bx = pc[3 * n]; by = pc[3 * n + 1]; bz = pc[3 * n + 2];
            b2 = fmaf(bx, bx, fmaf(by, by, bz * bz));
        }
        bx2[k] = pk2(bx, bx); by2[k] = pk2(by, by);
        bz2[k] = pk2(bz, bz); b2p[k] = pk2(b2, b2);
    }

    // acc[2s+0]: queries 0,1 for m-pair slot s (bytes 0,1 / 2,3);
    // acc[2s+1]: queries 2,3. Each byte +1 per 4-pair iter (<=95) — no overflow.
    u32 acc[8] = {0, 0, 0, 0, 0, 0, 0, 0};
#pragma unroll 1
    for (int j = 0; j < np4; j += 4) {
        const ulonglong2* P = sh + 2 * j;
        ulonglong2 A[4], B[4];
#pragma unroll
        for (int s = 0; s < 4; ++s) { A[s] = P[2 * s]; B[s] = P[2 * s + 1]; }
#pragma unroll
        for (int s = 0; s < 4; ++s) {
            u32 q0 = pair_sign(A[s].x, A[s].y, B[s].x, B[s].y,
                               bx2[0], by2[0], bz2[0], b2p[0], 0x00FBu);
            u32 q1 = pair_sign(A[s].x, A[s].y, B[s].x, B[s].y,
                               bx2[1], by2[1], bz2[1], b2p[1], 0xFB00u);
            acc[2 * s] += (q0 & 0x00000101u) + (q1 & 0x01010000u);
            u32 q2 = pair_sign(A[s].x, A[s].y, B[s].x, B[s].y,
                               bx2[2], by2[2], bz2[2], b2p[2], 0x00FBu);
            u32 q3 = pair_sign(A[s].x, A[s].y, B[s].x, B[s].y,
                               bx2[3], by2[3], bz2[3], b2p[3], 0xFB00u);
            acc[2 * s + 1] += (q2 & 0x00000101u) + (q3 & 0x01010000u);
        }
    }

    // Unsigned per-byte reduction, separated per query (bytes <= 95).
    u32 c[QPT] = {0, 0, 0, 0};
#pragma unroll
    for (int s = 0; s < 4; ++s) {
        u32 a = acc[2 * s], b = acc[2 * s + 1];
        c[0] += (a & 0xFFu) + ((a >> 8) & 0xFFu);
        c[1] += ((a >> 16) & 0xFFu) + (a >> 24);
        c[2] += (b & 0xFFu) + ((b >> 8) & 0xFFu);
        c[3] += ((b >> 16) & 0xFFu) + (b >> 24);
    }
#pragma unroll
    for (int k = 0; k < QPT; ++k) {
        int n = n0 + k * THREADS;
        if (n < N) atomicAdd(out + n, (float)c[k]);
    }
}

extern "C" void kernel_launch(void* const* d_in, const int* in_sizes, int n_in,
                              void* d_out, int out_size) {
    // The input with 3*out_size elements IS the pointcloud (output rows = N).
    int N = out_size;
    const float* pc;
    const float* pad;
    int M;
    if (in_sizes[0] == 3 * out_size) {
        pc  = (const float*)d_in[0];
        pad = (const float*)d_in[1];
        M   = in_sizes[1] / 3;
    } else {
        pc  = (const float*)d_in[1];
        pad = (const float*)d_in[0];
        M   = in_sizes[0] / 3;
    }

    int pairs  = (M + 1) / 2;                        // 12500
    int msplit = (pairs + MAX_PPS - 1) / MAX_PPS;    // 33
    if (msplit < 1) msplit = 1;
    int pps    = (pairs + msplit - 1) / msplit;      // 379 (<= 380)

    int nx = (N + QPB - 1) / QPB;                    // 40
    float* out = (float*)d_out;
    // Zero output (atomic accumulation target); memset node is graph-capturable.
    cudaMemsetAsync(out, 0, (size_t)out_size * sizeof(float), 0);
    dim3 grid(nx, msplit);                           // 40 x 33 = 1320 blocks
    count_kernel<<<grid, THREADS>>>(pc, pad, N, M, pairs, pps, out);
}

// round 12
// speedup vs baseline: 1.1416x; 1.1416x over previous
#include <cuda_runtime.h>
#include <math.h>

#define THREADS    128
#define QPT        4                 // queries per thread
#define QPB        (THREADS * QPT)   // 512 queries per block
#define TILE_PAIRS 576               // smem: 576 * 32B = 18,432 B (incl. prefetch pad)
#define MAX_PPS    572               // pps <= 572; ceil(572/4)=143 <= 255 byte bound

typedef unsigned long long u64;
typedef unsigned int u32;

__device__ __forceinline__ u64 pk2(float a, float b) {
    u64 r; asm("mov.b64 %0, {%1, %2};" : "=l"(r) : "f"(a), "f"(b)); return r;
}

// One m-pair (2 m's in f32x2 lanes) vs one query: s = d2 - 0.25 per lane,
// then sign bytes via PRMT. ctl 0x00FB -> sign bytes at {0,1}; 0xFB00 -> {2,3}.
__device__ __forceinline__ u32 pair_sign(u64 X, u64 Y, u64 Z, u64 C,
                                         u64 bx2, u64 by2, u64 bz2, u64 b2p,
                                         u32 ctl) {
    u32 q;
    asm("{\n\t"
        ".reg .b64 t;\n\t"
        ".reg .b32 lo, hi;\n\t"
        "fma.rn.f32x2 t, %1, %2, %3;\n\t"     // t  = bx*X + C
        "fma.rn.f32x2 t, %4, %5, t;\n\t"      // t += by*Y
        "fma.rn.f32x2 t, %6, %7, t;\n\t"      // t += bz*Z
        "add.rn.f32x2 t, t, %8;\n\t"          // t += b2
        "mov.b64 {lo, hi}, t;\n\t"
        "prmt.b32 %0, lo, hi, %9;\n\t"
        "}"
        : "=r"(q)
        : "l"(bx2), "l"(X), "l"(C),
          "l"(by2), "l"(Y),
          "l"(bz2), "l"(Z),
          "l"(b2p), "r"(ctl));
    return q;
}

// s = b2 + (a2-0.25) - 2(x*bx+y*by+z*bz) = d2 - 0.25; count iff s < 0.
// Matches reference's sqrt(max(d2,0)) <= 0.5 up to reassociation ties (8.1e-6).
__global__ void __launch_bounds__(THREADS, 6) count_kernel(
    const float* __restrict__ pc,   // queries [N,3]
    const float* __restrict__ pad,  // padding [M,3]
    int N, int M, int pairs, int pps, float* __restrict__ out)
{
    __shared__ ulonglong2 sh[2 * TILE_PAIRS];   // per pair: {X01,Y01},{Z01,C01}
    const float INF = __int_as_float(0x7f800000);

    int p0 = blockIdx.y * pps;
    int np = pairs - p0;
    if (np > pps) np = pps;
    int np4 = (np + 3) & ~3;        // multiple of 4 pairs (two 2-pair stages)
    int npad = np4 + 2;             // +2 sentinel pairs for branch-free prefetch

    // Stage + pack this m-slice from raw padding data.
    for (int i = threadIdx.x; i < np; i += THREADS) {
        int p  = p0 + i;
        int m0 = 2 * p, m1 = 2 * p + 1;
        float x0 = pad[3 * m0], y0 = pad[3 * m0 + 1], z0 = pad[3 * m0 + 2];
        float c0 = fmaf(x0, x0, fmaf(y0, y0, z0 * z0)) - 0.25f;
        float x1 = 0.f, y1 = 0.f, z1 = 0.f, c1 = INF;   // sentinel never counts
        if (m1 < M) {
            x1 = pad[3 * m1]; y1 = pad[3 * m1 + 1]; z1 = pad[3 * m1 + 2];
            c1 = fmaf(x1, x1, fmaf(y1, y1, z1 * z1)) - 0.25f;
        }
        sh[2 * i]     = make_ulonglong2(pk2(-2.f * x0, -2.f * x1),
                                        pk2(-2.f * y0, -2.f * y1));
        sh[2 * i + 1] = make_ulonglong2(pk2(-2.f * z0, -2.f * z1),
                                        pk2(c0, c1));
    }
    for (int i = np + threadIdx.x; i < npad; i += THREADS) {
        sh[2 * i]     = make_ulonglong2(0ull, 0ull);
        sh[2 * i + 1] = make_ulonglong2(0ull, pk2(INF, INF));
    }
    __syncthreads();

    // 4 queries per thread: n0 + k*THREADS.
    int n0 = blockIdx.x * QPB + threadIdx.x;
    u64 bx2[QPT], by2[QPT], bz2[QPT], b2p[QPT];
#pragma unroll
    for (int k = 0; k < QPT; ++k) {
        int n = n0 + k * THREADS;
        float bx = 0.f, by = 0.f, bz = 0.f, b2 = INF;
        if (n < N) {
            bx = pc[3 * n]; by = pc[3 * n + 1]; bz = pc[3 * n + 2];
            b2 = fmaf(bx, bx, fmaf(by, by, bz * bz));
        }
        bx2[k] = pk2(bx, bx); by2[k] = pk2(by, by);
        bz2[k] = pk2(bz, bz); b2p[k] = pk2(b2, b2);
    }

    // Software-pipelined mainloop: stage = 2 pairs in registers; each stage
    // prefetches the next stage's 4 LDS.128 before computing, hiding LDS
    // latency behind the 8 pair_sign chains. Two stages per loop iteration
    // alternate acc banks: each acc byte +1 per 2 stages (<=143, no overflow).
    u32 acc[8] = {0, 0, 0, 0, 0, 0, 0, 0};

    ulonglong2 cA0 = sh[0], cB0 = sh[1], cA1 = sh[2], cB1 = sh[3];

#define STAGE(BANK)                                                            \
    do {                                                                       \
        u32 q0 = pair_sign(cA0.x, cA0.y, cB0.x, cB0.y,                         \
                           bx2[0], by2[0], bz2[0], b2p[0], 0x00FBu);           \
        u32 q1 = pair_sign(cA0.x, cA0.y, cB0.x, cB0.y,                         \
                           bx2[1], by2[1], bz2[1], b2p[1], 0xFB00u);           \
        acc[(BANK) + 0] += (q0 & 0x00000101u) + (q1 & 0x01010000u);            \
        u32 q2 = pair_sign(cA0.x, cA0.y, cB0.x, cB0.y,                         \
                           bx2[2], by2[2], bz2[2], b2p[2], 0x00FBu);           \
        u32 q3 = pair_sign(cA0.x, cA0.y, cB0.x, cB0.y,                         \
                           bx2[3], by2[3], bz2[3], b2p[3], 0xFB00u);           \
        acc[(BANK) + 1] += (q2 & 0x00000101u) + (q3 & 0x01010000u);            \
        u32 r0 = pair_sign(cA1.x, cA1.y, cB1.x, cB1.y,                         \
                           bx2[0], by2[0], bz2[0], b2p[0], 0x00FBu);           \
        u32 r1 = pair_sign(cA1.x, cA1.y, cB1.x, cB1.y,                         \
                           bx2[1], by2[1], bz2[1], b2p[1], 0xFB00u);           \
        acc[(BANK) + 2] += (r0 & 0x00000101u) + (r1 & 0x01010000u);            \
        u32 r2 = pair_sign(cA1.x, cA1.y, cB1.x, cB1.y,                         \
                           bx2[2], by2[2], bz2[2], b2p[2], 0x00FBu);           \
        u32 r3 = pair_sign(cA1.x, cA1.y, cB1.x, cB1.y,                         \
                           bx2[3], by2[3], bz2[3], b2p[3], 0xFB00u);           \
        acc[(BANK) + 3] += (r2 & 0x00000101u) + (r3 & 0x01010000u);            \
    } while (0)

    for (int j = 0; j < np4; j += 4) {
        // ---- stage A: pairs j, j+1 (prefetch j+2, j+3 first) ----
        const ulonglong2* Pn = sh + 2 * (j + 2);
        ulonglong2 nA0 = Pn[0], nB0 = Pn[1], nA1 = Pn[2], nB1 = Pn[3];
        STAGE(0);
        cA0 = nA0; cB0 = nB0; cA1 = nA1; cB1 = nB1;

        // ---- stage B: pairs j+2, j+3 (prefetch j+4, j+5 first) ----
        const ulonglong2* Pm = sh + 2 * (j + 4);
        ulonglong2 mA0 = Pm[0], mB0 = Pm[1], mA1 = Pm[2], mB1 = Pm[3];
        STAGE(4);
        cA0 = mA0; cB0 = mB0; cA1 = mA1; cB1 = mB1;
    }
#undef STAGE

    // Unsigned per-byte reduction, separated per query (bytes <= 143).
    u32 c[QPT] = {0, 0, 0, 0};
#pragma unroll
    for (int s = 0; s < 2; ++s) {           // slot (m-pair position in stage)
#pragma unroll
        for (int bank = 0; bank < 8; bank += 4) {
            u32 a = acc[bank + 2 * s], b = acc[bank + 2 * s + 1];
            c[0] += (a & 0xFFu) + ((a >> 8) & 0xFFu);
            c[1] += ((a >> 16) & 0xFFu) + (a >> 24);
            c[2] += (b & 0xFFu) + ((b >> 8) & 0xFFu);
            c[3] += ((b >> 16) & 0xFFu) + (b >> 24);
        }
    }
#pragma unroll
    for (int k = 0; k < QPT; ++k) {
        int n = n0 + k * THREADS;
        if (n < N) atomicAdd(out + n, (float)c[k]);
    }
}

extern "C" void kernel_launch(void* const* d_in, const int* in_sizes, int n_in,
                              void* d_out, int out_size) {
    // The input with 3*out_size elements IS the pointcloud (output rows = N).
    int N = out_size;
    const float* pc;
    const float* pad;
    int M;
    if (in_sizes[0] == 3 * out_size) {
        pc  = (const float*)d_in[0];
        pad = (const float*)d_in[1];
        M   = in_sizes[1] / 3;
    } else {
        pc  = (const float*)d_in[1];
        pad = (const float*)d_in[0];
        M   = in_sizes[0] / 3;
    }

    int pairs  = (M + 1) / 2;                        // 12500
    int msplit = (pairs + MAX_PPS - 1) / MAX_PPS;    // 22
    if (msplit < 1) msplit = 1;
    int pps    = (pairs + msplit - 1) / msplit;      // 569 (<= 572)

    int nx = (N + QPB - 1) / QPB;                    // 40
    float* out = (float*)d_out;
    // Zero output (atomic accumulation target); memset node is graph-capturable.
    cudaMemsetAsync(out, 0, (size_t)out_size * sizeof(float), 0);
    dim3 grid(nx, msplit);                           // 40 x 22 = 880 blocks
    count_kernel<<<grid, THREADS>>>(pc, pad, N, M, pairs, pps, out);
}